// round 1
// baseline (speedup 1.0000x reference)
#include <cuda_runtime.h>
#include <cuda_bf16.h>

// Problem dims
#define MM 16384   // batch B
#define DD 512     // input dim
#define UU 512     // units
#define KK 1024    // D + U (fused GEMM K)
#define NN 2048    // 4*U

// GEMM tiling
#define BM 128
#define BN 128
#define BK 32
#define NKT (KK / BK)
#define LDT 40                 // padded leading dim (elems) for a 32-wide K tile
#define TILE_ELEMS (BM * LDT)  // 5120

// ---------------- device scratch (no allocation allowed) ----------------
__device__ __align__(16) __nv_bfloat16 g_Ahi[(size_t)MM * KK];
__device__ __align__(16) __nv_bfloat16 g_Alo[(size_t)MM * KK];
__device__ __align__(16) __nv_bfloat16 g_Bhi[(size_t)NN * KK];
__device__ __align__(16) __nv_bfloat16 g_Blo[(size_t)NN * KK];
__device__ float g_z[(size_t)MM * NN];

__device__ __forceinline__ void split_bf16(float v, __nv_bfloat16& hi, __nv_bfloat16& lo) {
    hi = __float2bfloat16_rn(v);
    lo = __float2bfloat16_rn(v - __bfloat162float(hi));
}

// ---------------- prep: A = [x | h] split into bf16 hi/lo ----------------
__global__ void prep_A_kernel(const float* __restrict__ x, const float* __restrict__ h) {
    size_t i = (size_t)blockIdx.x * blockDim.x + threadIdx.x;
    size_t total = (size_t)MM * KK / 4;
    if (i >= total) return;
    size_t idx = i * 4;
    int b = (int)(idx / KK);
    int k = (int)(idx % KK);
    const float* src = (k < DD) ? (x + (size_t)b * DD + k)
                                : (h + (size_t)b * UU + (k - DD));
    float4 v = *reinterpret_cast<const float4*>(src);
    float vv[4] = {v.x, v.y, v.z, v.w};
#pragma unroll
    for (int j = 0; j < 4; j++) {
        __nv_bfloat16 hi, lo;
        split_bf16(vv[j], hi, lo);
        g_Ahi[idx + j] = hi;
        g_Alo[idx + j] = lo;
    }
}

// ---------------- prep: B^T[n][k] = Wfull[k][n], split bf16 hi/lo ----------------
__global__ void prep_B_kernel(const float* __restrict__ Wk, const float* __restrict__ Wr) {
    __shared__ float t[32][33];
    int n0 = blockIdx.x * 32, k0 = blockIdx.y * 32;
    int tn = threadIdx.x, tk = threadIdx.y;  // block (32, 8)
#pragma unroll
    for (int j = 0; j < 32; j += 8) {
        int k = k0 + tk + j;
        float v = (k < DD) ? Wk[(size_t)k * NN + n0 + tn]
                           : Wr[(size_t)(k - DD) * NN + n0 + tn];
        t[tk + j][tn] = v;
    }
    __syncthreads();
#pragma unroll
    for (int j = 0; j < 32; j += 8) {
        int n = n0 + tk + j;
        int k = k0 + tn;
        __nv_bfloat16 hi, lo;
        split_bf16(t[tn][tk + j], hi, lo);
        g_Bhi[(size_t)n * KK + k] = hi;
        g_Blo[(size_t)n * KK + k] = lo;
    }
}

// ---------------- GEMM: z = A @ B^T via bf16x3 mma.sync ----------------
struct Stage {
    __nv_bfloat16 Ahi[TILE_ELEMS];
    __nv_bfloat16 Alo[TILE_ELEMS];
    __nv_bfloat16 Bhi[TILE_ELEMS];
    __nv_bfloat16 Blo[TILE_ELEMS];
};  // 40960 bytes

__device__ __forceinline__ void cp_async16(void* dst, const void* src) {
    unsigned d = (unsigned)__cvta_generic_to_shared(dst);
    asm volatile("cp.async.cg.shared.global [%0], [%1], 16;" :: "r"(d), "l"(src) : "memory");
}

__device__ __forceinline__ void mma16816(float c[4], const unsigned a[4], const unsigned b[2]) {
    asm volatile(
        "mma.sync.aligned.m16n8k16.row.col.f32.bf16.bf16.f32 "
        "{%0,%1,%2,%3}, {%4,%5,%6,%7}, {%8,%9}, {%0,%1,%2,%3};"
        : "+f"(c[0]), "+f"(c[1]), "+f"(c[2]), "+f"(c[3])
        : "r"(a[0]), "r"(a[1]), "r"(a[2]), "r"(a[3]), "r"(b[0]), "r"(b[1]));
}

__global__ void __launch_bounds__(256)
gemm_kernel() {
    extern __shared__ __align__(16) unsigned char smem_raw[];
    Stage* stages = reinterpret_cast<Stage*>(smem_raw);

    const int tid = threadIdx.x;
    const int lane = tid & 31;
    const int wid = tid >> 5;
    const int mw = (wid >> 1) * 32;  // 4 warps in M
    const int nw = (wid & 1) * 64;   // 2 warps in N
    const int m0 = blockIdx.y * BM;
    const int n0 = blockIdx.x * BN;
    const int r = lane >> 2, q = lane & 3;

    auto load_stage = [&](int s, int kt) {
        Stage* st = &stages[s];
        int k0 = kt * BK;
        for (int c = tid; c < 512; c += 256) {
            int row = c >> 2, seg = c & 3;
            int soff = row * LDT + seg * 8;
            size_t aoff = (size_t)(m0 + row) * KK + k0 + seg * 8;
            size_t boff = (size_t)(n0 + row) * KK + k0 + seg * 8;
            cp_async16(&st->Ahi[soff], &g_Ahi[aoff]);
            cp_async16(&st->Alo[soff], &g_Alo[aoff]);
            cp_async16(&st->Bhi[soff], &g_Bhi[boff]);
            cp_async16(&st->Blo[soff], &g_Blo[boff]);
        }
        asm volatile("cp.async.commit_group;" ::: "memory");
    };

    float acc[2][8][4];
#pragma unroll
    for (int a = 0; a < 2; a++)
#pragma unroll
        for (int b = 0; b < 8; b++)
#pragma unroll
            for (int c = 0; c < 4; c++) acc[a][b][c] = 0.0f;

    load_stage(0, 0);
    load_stage(1, 1);

    for (int kt = 0; kt < NKT; kt++) {
        asm volatile("cp.async.wait_group 1;" ::: "memory");
        __syncthreads();
        if (kt + 2 < NKT) load_stage((kt + 2) % 3, kt + 2);
        else asm volatile("cp.async.commit_group;" ::: "memory");

        const Stage* st = &stages[kt % 3];
#pragma unroll
        for (int kk = 0; kk < BK; kk += 16) {
            unsigned ah[2][4], al[2][4];
#pragma unroll
            for (int ms = 0; ms < 2; ms++) {
                int base = (mw + ms * 16 + r) * LDT + kk + 2 * q;
                ah[ms][0] = *(const unsigned*)&st->Ahi[base];
                ah[ms][1] = *(const unsigned*)&st->Ahi[base + 8 * LDT];
                ah[ms][2] = *(const unsigned*)&st->Ahi[base + 8];
                ah[ms][3] = *(const unsigned*)&st->Ahi[base + 8 * LDT + 8];
                al[ms][0] = *(const unsigned*)&st->Alo[base];
                al[ms][1] = *(const unsigned*)&st->Alo[base + 8 * LDT];
                al[ms][2] = *(const unsigned*)&st->Alo[base + 8];
                al[ms][3] = *(const unsigned*)&st->Alo[base + 8 * LDT + 8];
            }
#pragma unroll
            for (int ns = 0; ns < 8; ns++) {
                int bb = (nw + ns * 8 + r) * LDT + kk + 2 * q;
                unsigned bh[2], bl[2];
                bh[0] = *(const unsigned*)&st->Bhi[bb];
                bh[1] = *(const unsigned*)&st->Bhi[bb + 8];
                bl[0] = *(const unsigned*)&st->Blo[bb];
                bl[1] = *(const unsigned*)&st->Blo[bb + 8];
#pragma unroll
                for (int ms = 0; ms < 2; ms++) {
                    mma16816(acc[ms][ns], ah[ms], bh);  // hi*hi
                    mma16816(acc[ms][ns], ah[ms], bl);  // hi*lo
                    mma16816(acc[ms][ns], al[ms], bh);  // lo*hi
                }
            }
        }
    }

    // epilogue: write z (bias added later in gate kernel)
#pragma unroll
    for (int ms = 0; ms < 2; ms++)
#pragma unroll
        for (int ns = 0; ns < 8; ns++) {
            int row = m0 + mw + ms * 16 + r;
            int col = n0 + nw + ns * 8 + 2 * q;
            *(float2*)&g_z[(size_t)row * NN + col] =
                make_float2(acc[ms][ns][0], acc[ms][ns][1]);
            *(float2*)&g_z[(size_t)(row + 8) * NN + col] =
                make_float2(acc[ms][ns][2], acc[ms][ns][3]);
        }
}

// ---------------- gates ----------------
__device__ __forceinline__ float sigf(float x) {
    return 1.0f / (1.0f + __expf(-x));
}

__global__ void gates_kernel(const float* __restrict__ c_tm1,
                             const float* __restrict__ pw,
                             const float* __restrict__ bias,
                             float* __restrict__ out) {
    int i = blockIdx.x * blockDim.x + threadIdx.x;
    if (i >= MM * UU / 4) return;
    int b = i / (UU / 4);
    int u = (i % (UU / 4)) * 4;
    const float* zrow = g_z + (size_t)b * NN;
    float4 zi = *(const float4*)(zrow + u);
    float4 zf = *(const float4*)(zrow + 512 + u);
    float4 zg = *(const float4*)(zrow + 1024 + u);
    float4 zo = *(const float4*)(zrow + 1536 + u);
    float4 cp4 = *(const float4*)(c_tm1 + (size_t)b * UU + u);
    float4 bi = *(const float4*)(bias + u);
    float4 bff = *(const float4*)(bias + 512 + u);
    float4 bg = *(const float4*)(bias + 1024 + u);
    float4 bo = *(const float4*)(bias + 1536 + u);

    const float* zia = (const float*)&zi;
    const float* zfa = (const float*)&zf;
    const float* zga = (const float*)&zg;
    const float* zoa = (const float*)&zo;
    const float* cpa = (const float*)&cp4;
    const float* bia = (const float*)&bi;
    const float* bfa = (const float*)&bff;
    const float* bga = (const float*)&bg;
    const float* boa = (const float*)&bo;

    float hv[4], cv[4];
#pragma unroll
    for (int j = 0; j < 4; j++) {
        float pwi = pw[(u + j) * 3 + 0];
        float pwf = pw[(u + j) * 3 + 1];
        float pwo = pw[(u + j) * 3 + 2];
        float cprev = cpa[j];
        float iv = sigf(zia[j] + bia[j] + cprev * pwi);
        float fv = sigf(zfa[j] + bfa[j] + cprev * pwf);
        float gv = tanhf(zga[j] + bga[j]);
        float cc = fv * cprev + iv * gv;
        float ov = sigf(zoa[j] + boa[j] + cc * pwo);
        hv[j] = ov * tanhf(cc);
        cv[j] = cc;
    }
    *(float4*)(out + (size_t)b * UU + u) = make_float4(hv[0], hv[1], hv[2], hv[3]);
    *(float4*)(out + (size_t)MM * UU + (size_t)b * UU + u) =
        make_float4(cv[0], cv[1], cv[2], cv[3]);
}

// ---------------- launch ----------------
extern "C" void kernel_launch(void* const* d_in, const int* in_sizes, int n_in,
                              void* d_out, int out_size) {
    const float* x    = (const float*)d_in[0];
    const float* h    = (const float*)d_in[1];
    const float* c    = (const float*)d_in[2];
    const float* Wk   = (const float*)d_in[3];
    const float* Wr   = (const float*)d_in[4];
    const float* pw   = (const float*)d_in[5];
    const float* bias = (const float*)d_in[6];
    float* out = (float*)d_out;

    cudaFuncSetAttribute(gemm_kernel, cudaFuncAttributeMaxDynamicSharedMemorySize,
                         (int)(3 * sizeof(Stage)));

    prep_A_kernel<<<(MM * KK / 4 + 255) / 256, 256>>>(x, h);
    prep_B_kernel<<<dim3(NN / 32, KK / 32), dim3(32, 8)>>>(Wk, Wr);
    gemm_kernel<<<dim3(NN / BN, MM / BM), 256, 3 * sizeof(Stage)>>>();
    gates_kernel<<<(MM * UU / 4 + 255) / 256, 256>>>(c, pw, bias, out);
}

// round 3
// speedup vs baseline: 1.0272x; 1.0272x over previous
#include <cuda_runtime.h>
#include <cuda_bf16.h>
#include <cuda_fp16.h>
#include <cstdint>

// ---------------- problem dims ----------------
#define MM 16384
#define DD 512
#define UU 512
#define KK 1024
#define NN 2048

// ---------------- GEMM tiling ----------------
#define BM 128
#define BN 128
#define BK 32
#define NKT (KK / BK)          // 32
#define LDT 40                 // padded leading dim (halfwords) for 32-wide K tile
#define TILE_ELEMS (BM * LDT)  // 5120

// ---------------- device scratch ----------------
__device__ __align__(16) __half         g_Ahi[(size_t)MM * KK];  // fp16(a)
__device__ __align__(16) __nv_bfloat16  g_Abf[(size_t)MM * KK];  // bf16(a)
__device__ __align__(16) __half         g_Bhi[(size_t)NN * KK];  // fp16(b), permuted rows
__device__ __align__(16) __nv_bfloat16  g_Blo[(size_t)NN * KK];  // bf16(b - fp16(b)), permuted

// ---------------- prep A ----------------
__global__ void __launch_bounds__(256) prep_A_kernel(const float* __restrict__ x,
                                                     const float* __restrict__ h) {
    int gi = blockIdx.x * 256 + threadIdx.x;     // one 8-elem group
    int b = gi >> 7;
    int k0 = (gi & 127) * 8;
    const float* src = (k0 < DD) ? (x + (size_t)b * DD + k0)
                                 : (h + (size_t)b * UU + (k0 - DD));
    float4 v0 = *reinterpret_cast<const float4*>(src);
    float4 v1 = *reinterpret_cast<const float4*>(src + 4);
    float v[8] = {v0.x, v0.y, v0.z, v0.w, v1.x, v1.y, v1.z, v1.w};
    __half hh[8];
    __nv_bfloat16 bb[8];
#pragma unroll
    for (int j = 0; j < 8; j++) {
        hh[j] = __float2half_rn(v[j]);
        bb[j] = __float2bfloat16_rn(v[j]);
    }
    size_t off = (size_t)b * KK + k0;
    *reinterpret_cast<uint4*>(&g_Ahi[off]) = *reinterpret_cast<uint4*>(hh);
    *reinterpret_cast<uint4*>(&g_Abf[off]) = *reinterpret_cast<uint4*>(bb);
}

// ---------------- prep B: transpose + permute (p = u*4 + gate) ----------------
__global__ void prep_B_kernel(const float* __restrict__ Wk, const float* __restrict__ Wr) {
    __shared__ float t[32][33];
    int n0 = blockIdx.x * 32, k0 = blockIdx.y * 32;
    int tn = threadIdx.x, tk = threadIdx.y;  // block (32, 8)
#pragma unroll
    for (int j = 0; j < 32; j += 8) {
        int k = k0 + tk + j;
        float v = (k < DD) ? Wk[(size_t)k * NN + n0 + tn]
                           : Wr[(size_t)(k - DD) * NN + n0 + tn];
        t[tk + j][tn] = v;
    }
    __syncthreads();
#pragma unroll
    for (int j = 0; j < 32; j += 8) {
        int n = n0 + tk + j;                 // original z column
        int k = k0 + tn;
        int p = ((n & 511) << 2) + (n >> 9); // permuted row: unit*4 + gate
        float v = t[tn][tk + j];
        __half hv = __float2half_rn(v);
        g_Bhi[(size_t)p * KK + k] = hv;
        g_Blo[(size_t)p * KK + k] = __float2bfloat16_rn(v - __half2float(hv));
    }
}

// ---------------- fused GEMM (2-pass mma.sync) + gates epilogue ----------------
struct Stage {
    __half        Ahi[TILE_ELEMS];
    __nv_bfloat16 Abf[TILE_ELEMS];
    __half        Bhi[TILE_ELEMS];
    __nv_bfloat16 Blo[TILE_ELEMS];
};  // 40960 bytes

__device__ __forceinline__ void cp_async16(void* dst, const void* src) {
    unsigned d = (unsigned)__cvta_generic_to_shared(dst);
    asm volatile("cp.async.cg.shared.global [%0], [%1], 16;" :: "r"(d), "l"(src) : "memory");
}

__device__ __forceinline__ void mma_f16(float c[4], const unsigned a[4], const unsigned b[2]) {
    asm volatile(
        "mma.sync.aligned.m16n8k16.row.col.f32.f16.f16.f32 "
        "{%0,%1,%2,%3}, {%4,%5,%6,%7}, {%8,%9}, {%0,%1,%2,%3};"
        : "+f"(c[0]), "+f"(c[1]), "+f"(c[2]), "+f"(c[3])
        : "r"(a[0]), "r"(a[1]), "r"(a[2]), "r"(a[3]), "r"(b[0]), "r"(b[1]));
}

__device__ __forceinline__ void mma_bf16(float c[4], const unsigned a[4], const unsigned b[2]) {
    asm volatile(
        "mma.sync.aligned.m16n8k16.row.col.f32.bf16.bf16.f32 "
        "{%0,%1,%2,%3}, {%4,%5,%6,%7}, {%8,%9}, {%0,%1,%2,%3};"
        : "+f"(c[0]), "+f"(c[1]), "+f"(c[2]), "+f"(c[3])
        : "r"(a[0]), "r"(a[1]), "r"(a[2]), "r"(a[3]), "r"(b[0]), "r"(b[1]));
}

__device__ __forceinline__ float sigf(float x) { return 1.0f / (1.0f + __expf(-x)); }

#define LDZ 132  // padded z stride in floats

__global__ void __launch_bounds__(256)
lstm_gemm_kernel(const float* __restrict__ c_tm1,
                 const float* __restrict__ pw,
                 const float* __restrict__ bias,
                 float* __restrict__ out) {
    extern __shared__ __align__(16) unsigned char smem_raw[];
    Stage* stages = reinterpret_cast<Stage*>(smem_raw);

    const int tid = threadIdx.x;
    const int lane = tid & 31;
    const int wid = tid >> 5;
    const int mw = (wid >> 1) * 32;  // 4 warps in M
    const int nw = (wid & 1) * 64;   // 2 warps in N
    const int m0 = blockIdx.y * BM;
    const int n0 = blockIdx.x * BN;  // permuted-col tile base
    const int r = lane >> 2, q = lane & 3;

    auto load_stage = [&](int s, int kt) {
        Stage* st = &stages[s];
        int k0 = kt * BK;
        for (int c = tid; c < 512; c += 256) {
            int row = c >> 2, seg = c & 3;
            int soff = row * LDT + seg * 8;
            size_t aoff = (size_t)(m0 + row) * KK + k0 + seg * 8;
            size_t boff = (size_t)(n0 + row) * KK + k0 + seg * 8;
            cp_async16(&st->Ahi[soff], &g_Ahi[aoff]);
            cp_async16(&st->Abf[soff], &g_Abf[aoff]);
            cp_async16(&st->Bhi[soff], &g_Bhi[boff]);
            cp_async16(&st->Blo[soff], &g_Blo[boff]);
        }
        asm volatile("cp.async.commit_group;" ::: "memory");
    };

    float acc[2][8][4];
#pragma unroll
    for (int a = 0; a < 2; a++)
#pragma unroll
        for (int b = 0; b < 8; b++)
#pragma unroll
            for (int c = 0; c < 4; c++) acc[a][b][c] = 0.0f;

    load_stage(0, 0);
    load_stage(1, 1);

    for (int kt = 0; kt < NKT; kt++) {
        asm volatile("cp.async.wait_group 1;" ::: "memory");
        __syncthreads();
        if (kt + 2 < NKT) load_stage((kt + 2) % 3, kt + 2);
        else asm volatile("cp.async.commit_group;" ::: "memory");

        const Stage* st = &stages[kt % 3];
#pragma unroll
        for (int kk = 0; kk < BK; kk += 16) {
            unsigned ah[2][4], ab[2][4];
#pragma unroll
            for (int ms = 0; ms < 2; ms++) {
                int base = (mw + ms * 16 + r) * LDT + kk + 2 * q;
                ah[ms][0] = *(const unsigned*)&st->Ahi[base];
                ah[ms][1] = *(const unsigned*)&st->Ahi[base + 8 * LDT];
                ah[ms][2] = *(const unsigned*)&st->Ahi[base + 8];
                ah[ms][3] = *(const unsigned*)&st->Ahi[base + 8 * LDT + 8];
                ab[ms][0] = *(const unsigned*)&st->Abf[base];
                ab[ms][1] = *(const unsigned*)&st->Abf[base + 8 * LDT];
                ab[ms][2] = *(const unsigned*)&st->Abf[base + 8];
                ab[ms][3] = *(const unsigned*)&st->Abf[base + 8 * LDT + 8];
            }
#pragma unroll
            for (int ns = 0; ns < 8; ns++) {
                int bb = (nw + ns * 8 + r) * LDT + kk + 2 * q;
                unsigned bh[2], bl[2];
                bh[0] = *(const unsigned*)&st->Bhi[bb];
                bh[1] = *(const unsigned*)&st->Bhi[bb + 8];
                bl[0] = *(const unsigned*)&st->Blo[bb];
                bl[1] = *(const unsigned*)&st->Blo[bb + 8];
#pragma unroll
                for (int ms = 0; ms < 2; ms++) {
                    mma_f16(acc[ms][ns], ah[ms], bh);   // fp16 main product
                    mma_bf16(acc[ms][ns], ab[ms], bl);  // bf16 correction
                }
            }
        }
    }

    // ---------------- fused gate epilogue ----------------
    __syncthreads();  // all mma done; safe to reuse stage smem as z-tile
    float* zsm = reinterpret_cast<float*>(smem_raw);  // [128][LDZ]

#pragma unroll
    for (int ms = 0; ms < 2; ms++)
#pragma unroll
        for (int ns = 0; ns < 8; ns++) {
            int row = mw + ms * 16 + r;
            int col = nw + ns * 8 + 2 * q;
            *(float2*)&zsm[row * LDZ + col] = make_float2(acc[ms][ns][0], acc[ms][ns][1]);
            *(float2*)&zsm[(row + 8) * LDZ + col] = make_float2(acc[ms][ns][2], acc[ms][ns][3]);
        }
    __syncthreads();

    {
        const int ul = tid & 31;             // local unit 0..31
        const int u = blockIdx.x * 32 + ul;  // global unit
        const float bi = bias[u];
        const float bf = bias[512 + u];
        const float bg = bias[1024 + u];
        const float bo = bias[1536 + u];
        const float pwi = pw[u * 3 + 0];
        const float pwf = pw[u * 3 + 1];
        const float pwo = pw[u * 3 + 2];
#pragma unroll
        for (int it = 0; it < 16; it++) {
            int row = (tid >> 5) * 16 + it;
            int m = m0 + row;
            float4 zz = *reinterpret_cast<const float4*>(&zsm[row * LDZ + ul * 4]);
            float cprev = c_tm1[(size_t)m * UU + u];
            float iv = sigf(zz.x + bi + cprev * pwi);
            float fv = sigf(zz.y + bf + cprev * pwf);
            float gv = tanhf(zz.z + bg);
            float cc = fv * cprev + iv * gv;
            float ov = sigf(zz.w + bo + cc * pwo);
            out[(size_t)m * UU + u] = ov * tanhf(cc);
            out[(size_t)MM * UU + (size_t)m * UU + u] = cc;
        }
    }
}

// ---------------- launch ----------------
extern "C" void kernel_launch(void* const* d_in, const int* in_sizes, int n_in,
                              void* d_out, int out_size) {
    const float* x    = (const float*)d_in[0];
    const float* h    = (const float*)d_in[1];
    const float* c    = (const float*)d_in[2];
    const float* Wk   = (const float*)d_in[3];
    const float* Wr   = (const float*)d_in[4];
    const float* pw   = (const float*)d_in[5];
    const float* bias = (const float*)d_in[6];
    float* out = (float*)d_out;

    cudaFuncSetAttribute(lstm_gemm_kernel, cudaFuncAttributeMaxDynamicSharedMemorySize,
                         (int)(3 * sizeof(Stage)));

    prep_A_kernel<<<(MM * KK / 8) / 256, 256>>>(x, h);
    prep_B_kernel<<<dim3(NN / 32, KK / 32), dim3(32, 8)>>>(Wk, Wr);
    lstm_gemm_kernel<<<dim3(NN / BN, MM / BM), 256, 3 * sizeof(Stage)>>>(c, pw, bias, out);
}